// round 13
// baseline (speedup 1.0000x reference)
#include <cuda_runtime.h>
#include <cuda_bf16.h>
#include <cstdint>

// ---------------------------------------------------------------------------
// BarbershopTransformer: 6-layer GPT forward, B=32 T=256 C=384 H=6 D=64 V=32000
// Round 13: permuted-fragment smem GEMM (LDS.128/LDS.64 fragment loads),
// register-pipelined global loads, BK=32. Fused QKV, pre-rounded tf32 weights,
// flash attention as before.
// ---------------------------------------------------------------------------

#define NL    6
#define C     384
#define HN    6
#define HD    64
#define TT    256
#define BB    32
#define M_TOK (BB*TT)          // 8192
#define FF    (4*C)            // 1536
#define V     32000
#define C3    (3*C)            // 1152

__device__ float g_x   [M_TOK*C];
__device__ float g_h   [M_TOK*C];
__device__ float g_att [M_TOK*C];
__device__ float g_mlp [M_TOK*FF];
__device__ float g_qkvb[M_TOK*C3];

#define WBUF_ORIG 35349248
#define WBUF_TOTAL (WBUF_ORIG + NL*C*C3)
__device__ float g_wbuf[WBUF_TOTAL];
__device__ int   g_in_bf16;
__device__ int   g_out_bf16;

__device__ __forceinline__ float* buf_sel(int s) {
    switch (s) {
        case 0: return g_x;
        case 1: return g_h;
        case 5: return g_att;
        case 6: return g_mlp;
        default: return g_qkvb;   // 7
    }
}

// ---------------------------------------------------------------------------
__device__ __forceinline__ float tf32r(float x) {
    float y;
    asm("cvt.rna.tf32.f32 %0, %1;" : "=f"(y) : "f"(x));
    return y;
}

__global__ void flags_kernel(const void* buf, int in_mode, int out_mode) {
    __shared__ int sh;
    int tid = threadIdx.x;
    if (tid == 0) sh = 0;
    __syncthreads();
    if (in_mode < 0) {
        const __nv_bfloat16* s = (const __nv_bfloat16*)buf;
        int cnt = 0;
        for (int i = tid; i < 4096; i += 256) {
            float f = __bfloat162float(s[i]);
            if (!isfinite(f) || fabsf(f) > 8.0f) cnt++;
        }
        atomicAdd(&sh, cnt);
    }
    __syncthreads();
    if (tid == 0) {
        int in_bf16 = (in_mode < 0) ? ((sh > 64) ? 0 : 1) : in_mode;
        g_in_bf16  = in_bf16;
        g_out_bf16 = (out_mode < 0) ? in_bf16 : out_mode;
    }
}

__global__ void convert_kernel(const void* src, long long off, int n, int rnd) {
    int i = blockIdx.x * blockDim.x + threadIdx.x;
    if (i >= n) return;
    float vv;
    if (g_in_bf16) vv = __bfloat162float(((const __nv_bfloat16*)src)[i]);
    else           vv = ((const float*)src)[i];
    if (rnd) vv = tf32r(vv);
    long long o = off + i;
    if (o >= 0 && o < WBUF_TOTAL) g_wbuf[o] = vv;
}

// Pack Wq|Wk|Wv -> [NL][C][3C]
__global__ void pack_qkv(long long oWq, long long oWk, long long oWv, long long dst) {
    int i = blockIdx.x * blockDim.x + threadIdx.x;
    if (i >= NL * C * C3) return;
    int n3  = i % C3;
    int rem = i / C3;          // l*C + k
    int part = n3 / C, n = n3 % C;
    long long src = (part == 0 ? oWq : part == 1 ? oWk : oWv) + (long long)rem * C + n;
    g_wbuf[dst + i] = g_wbuf[src];
}

// ---------------------------------------------------------------------------
__global__ void embed_kernel(const int* __restrict__ idx,
                             long long tokOff, long long posOff) {
    int m = blockIdx.x;
    int c = threadIdx.x;
    int t = m & (TT - 1);
    int tk = idx[m];
    if ((unsigned)tk >= (unsigned)V) tk = 0;
    const float* tok = g_wbuf + tokOff;
    const float* pos = g_wbuf + posOff;
    g_x[m * C + c] = tok[tk * C + c] + pos[t * C + c];
}

// ---------------------------------------------------------------------------
__global__ void ln_kernel(int inSel, long long gOff, long long bOff, int outSel,
                          int rnd) {
    __shared__ float red[4];
    __shared__ float stat[2];
    const float* x = buf_sel(inSel);
    float* out     = buf_sel(outSel);
    const float* g = g_wbuf + gOff;
    const float* b = g_wbuf + bOff;
    int row = blockIdx.x, tid = threadIdx.x;
    const float* xr = x + (size_t)row * C;
    float v0 = xr[tid], v1 = xr[tid + 128], v2 = xr[tid + 256];
    float s = v0 + v1 + v2;
    #pragma unroll
    for (int o = 16; o; o >>= 1) s += __shfl_xor_sync(0xffffffffu, s, o);
    if ((tid & 31) == 0) red[tid >> 5] = s;
    __syncthreads();
    if (tid == 0) stat[0] = (red[0] + red[1] + red[2] + red[3]) * (1.0f / C);
    __syncthreads();
    float m = stat[0];
    float d0 = v0 - m, d1 = v1 - m, d2 = v2 - m;
    float q = d0 * d0 + d1 * d1 + d2 * d2;
    #pragma unroll
    for (int o = 16; o; o >>= 1) q += __shfl_xor_sync(0xffffffffu, q, o);
    if ((tid & 31) == 0) red[tid >> 5] = q;
    __syncthreads();
    if (tid == 0)
        stat[1] = rsqrtf((red[0] + red[1] + red[2] + red[3]) * (1.0f / C) + 1e-5f);
    __syncthreads();
    float r = stat[1];
    float* o = out + (size_t)row * C;
    float o0 = d0 * r * g[tid]       + b[tid];
    float o1 = d1 * r * g[tid + 128] + b[tid + 128];
    float o2 = d2 * r * g[tid + 256] + b[tid + 256];
    if (rnd) { o0 = tf32r(o0); o1 = tf32r(o1); o2 = tf32r(o2); }
    o[tid] = o0; o[tid + 128] = o1; o[tid + 256] = o2;
}

// ---------------------------------------------------------------------------
__device__ __forceinline__ void mma_tf32(float& c0, float& c1, float& c2, float& c3,
                                         uint32_t a0, uint32_t a1, uint32_t a2, uint32_t a3,
                                         uint32_t b0, uint32_t b1) {
    asm volatile(
        "mma.sync.aligned.m16n8k8.row.col.f32.tf32.tf32.f32 "
        "{%0,%1,%2,%3}, {%4,%5,%6,%7}, {%8,%9}, {%0,%1,%2,%3};\n"
        : "+f"(c0), "+f"(c1), "+f"(c2), "+f"(c3)
        : "r"(a0), "r"(a1), "r"(a2), "r"(a3), "r"(b0), "r"(b1));
}

// ---------------------------------------------------------------------------
// Permuted-fragment tf32 GEMM: C[M,N] = A[M,K] @ B[K,N]. BM=BN=128, BK=32,
// 256 thr (8 warps of 64x32). Smem tiles stored in mma-fragment order:
//   As[(r*4+kk8)*32 + lane][0..3]  (4096 floats, 16KB)  -> LDS.128 per mi
//   Bs[(kk8*16+cb)*32 + lane][0..1] (4096 floats, 16KB) -> LDS.64  per ni
// Register-pipelined global loads (LDG next tile during compute).
template<bool BIAS, bool RELU, bool RES, bool ROUND, bool DYNOUT>
__global__ void __launch_bounds__(256, 2)
mma_gemm(int aSel, long long bOff, long long biasOff,
         int outSel, void* dOutPtr, int M, int N, int K, int Mlim) {
    __shared__ float As[4096];
    __shared__ float Bs[4096];
    const float* A  = buf_sel(aSel);
    const float* B  = g_wbuf + bOff;
    const float* bi = g_wbuf + biasOff;

    int tid = threadIdx.x;
    int warp = tid >> 5, lane = tid & 31;
    int wm = warp >> 2;          // 0..1
    int wn = warp & 3;           // 0..3
    int g = lane >> 2, t = lane & 3;
    int bm = blockIdx.y * 128, bn = blockIdx.x * 128;

    // per-thread staging coordinates (4 float4 each for A and B per stage)
    int arow[4], akq[4], brk[4], bnq[4];
    #pragma unroll
    for (int u = 0; u < 4; u++) {
        int f = tid + u * 256;           // 0..1023
        arow[u] = f >> 3;  akq[u] = f & 7;     // A: row 0..127, k-quad 0..7
        brk[u]  = f >> 5;  bnq[u] = f & 31;    // B: k-row 0..31, n-quad 0..31
    }
    // precomputed permuted STS addresses (element 0 of each quad)
    int aAddr[4], bAddr[4];
    #pragma unroll
    for (int u = 0; u < 4; u++) {
        int r = arow[u] >> 4, gg = arow[u] & 7, hi = (arow[u] >> 3) & 1;
        int kk8 = akq[u] >> 1, lo4 = akq[u] & 1;
        aAddr[u] = ((r * 4 + kk8) * 32 + gg * 4) * 4 + (hi + 2 * lo4);
        int k8 = brk[u] >> 3, slot = (brk[u] >> 2) & 1, tt = brk[u] & 3;
        bAddr[u] = (k8 * 16) * 64 + tt * 2 + slot;  // + (cb*32+g*4)*2 per elem
    }

    float acc[4][4][4];
    #pragma unroll
    for (int mi = 0; mi < 4; mi++)
        #pragma unroll
        for (int ni = 0; ni < 4; ni++)
            #pragma unroll
            for (int cc = 0; cc < 4; cc++) acc[mi][ni][cc] = 0.f;

    int ns = K >> 5;   // stages of BK=32
    float4 aR[4], bR[4];

    // prologue: load stage 0
    #pragma unroll
    for (int u = 0; u < 4; u++) {
        aR[u] = *(const float4*)(A + (size_t)(bm + arow[u]) * K + akq[u] * 4);
        bR[u] = *(const float4*)(B + (size_t)brk[u] * N + bn + bnq[u] * 4);
    }

    for (int s = 0; s < ns; s++) {
        // store staged regs to permuted smem
        #pragma unroll
        for (int u = 0; u < 4; u++) {
            As[aAddr[u]]      = aR[u].x;
            As[aAddr[u] + 4]  = aR[u].y;
            As[aAddr[u] + 8]  = aR[u].z;
            As[aAddr[u] + 12] = aR[u].w;
            int n0 = bnq[u] * 4;
            #pragma unroll
            for (int j = 0; j < 4; j++) {
                int n = n0 + j;
                int cb = n >> 3, gg = n & 7;
                float v = (j == 0) ? bR[u].x : (j == 1) ? bR[u].y
                        : (j == 2) ? bR[u].z : bR[u].w;
                Bs[bAddr[u] + (cb * 32 + gg * 4) * 2] = v;
            }
        }
        __syncthreads();

        // prefetch next stage into registers (overlaps with MMA below)
        if (s + 1 < ns) {
            int k0n = (s + 1) << 5;
            #pragma unroll
            for (int u = 0; u < 4; u++) {
                aR[u] = *(const float4*)(A + (size_t)(bm + arow[u]) * K + k0n + akq[u] * 4);
                bR[u] = *(const float4*)(B + (size_t)(k0n + brk[u]) * N + bn + bnq[u] * 4);
            }
        }

        #pragma unroll
        for (int kk8 = 0; kk8 < 4; kk8++) {
            float4 af[4];
            #pragma unroll
            for (int mi = 0; mi < 4; mi++) {
                int r = wm * 4 + mi;
                af[mi] = *(const float4*)(As + ((r * 4 + kk8) * 32 + lane) * 4);
            }
            float2 bf[4];
            #pragma unroll
            for (int ni = 0; ni < 4; ni++) {
                int cb = wn * 4 + ni;
                bf[ni] = *(const float2*)(Bs + ((kk8 * 16 + cb) * 32 + lane) * 2);
            }
            #pragma unroll
            for (int mi = 0; mi < 4; mi++)
                #pragma unroll
                for (int ni = 0; ni < 4; ni++)
                    mma_tf32(acc[mi][ni][0], acc[mi][ni][1],
                             acc[mi][ni][2], acc[mi][ni][3],
                             __float_as_uint(af[mi].x), __float_as_uint(af[mi].y),
                             __float_as_uint(af[mi].z), __float_as_uint(af[mi].w),
                             __float_as_uint(bf[ni].x), __float_as_uint(bf[ni].y));
        }
        __syncthreads();
    }

    // epilogue
    bool store_bf16 = DYNOUT ? (g_out_bf16 != 0) : false;
    float* outBuf = DYNOUT ? nullptr : buf_sel(outSel);
    #pragma unroll
    for (int mi = 0; mi < 4; mi++) {
        #pragma unroll
        for (int ni = 0; ni < 4; ni++) {
            int col = bn + wn * 32 + ni * 8 + t * 2;
            float b0 = 0.f, b1 = 0.f;
            if (BIAS) { b0 = bi[col]; b1 = bi[col + 1]; }
            #pragma unroll
            for (int half = 0; half < 2; half++) {
                int row = bm + wm * 64 + mi * 16 + g + half * 8;
                if (row >= Mlim) continue;
                float v0 = acc[mi][ni][half * 2 + 0];
                float v1 = acc[mi][ni][half * 2 + 1];
                if (BIAS) { v0 += b0; v1 += b1; }
                if (RELU) { v0 = fmaxf(v0, 0.f); v1 = fmaxf(v1, 0.f); }
                long long base = (long long)row * N + col;
                if (RES) {
                    float2 rr = *(const float2*)(g_x + base);
                    v0 += rr.x; v1 += rr.y;
                }
                if (ROUND) { v0 = tf32r(v0); v1 = tf32r(v1); }
                if (DYNOUT) {
                    if (store_bf16) {
                        __nv_bfloat162 pk = __floats2bfloat162_rn(v0, v1);
                        *(__nv_bfloat162*)((__nv_bfloat16*)dOutPtr + base) = pk;
                    } else {
                        *(float2*)((float*)dOutPtr + base) = make_float2(v0, v1);
                    }
                } else {
                    *(float2*)(outBuf + base) = make_float2(v0, v1);
                }
            }
        }
    }
}

// ---------------------------------------------------------------------------
// Flash attention on the fused qkv buffer [M, 1152]: q|k|v at col 0/384/768.
#define KSTR 65
#define QS   C3
__global__ void __launch_bounds__(256)
flash_attn() {
    __shared__ float Ks[64 * KSTR];
    __shared__ float Vs[64 * 64];
    __shared__ float Ps[8][4][64];
    int blk = blockIdx.x;
    int qt = blk & 7;
    int bh = blk >> 3;
    int b = bh / HN, h = bh % HN;
    int tid = threadIdx.x, w = tid >> 5, lane = tid & 31;
    int qbase = qt * 32 + w * 4;
    const float scale = rsqrtf((float)C);

    float q[4][2];
    #pragma unroll
    for (int qi = 0; qi < 4; qi++) {
        long long base = (long long)(b * TT + qbase + qi) * QS + h * HD;
        q[qi][0] = g_qkvb[base + lane]      * scale;
        q[qi][1] = g_qkvb[base + lane + 32] * scale;
    }
    float o[4][2];
    float m[4], l[4];
    #pragma unroll
    for (int qi = 0; qi < 4; qi++) {
        o[qi][0] = o[qi][1] = 0.f;
        m[qi] = -1e30f; l[qi] = 0.f;
    }

    int nch = (qt * 32 + 31) / 64 + 1;
    for (int c = 0; c < nch; c++) {
        __syncthreads();
        #pragma unroll
        for (int u = 0; u < 4; u++) {
            int f = tid + u * 256;
            int r = f >> 4, dc = (f & 15) * 4;
            long long gb = (long long)(b * TT + c * 64 + r) * QS + h * HD + dc;
            float4 kv = *(const float4*)(g_qkvb + gb + C);
            Ks[r * KSTR + dc]     = kv.x;
            Ks[r * KSTR + dc + 1] = kv.y;
            Ks[r * KSTR + dc + 2] = kv.z;
            Ks[r * KSTR + dc + 3] = kv.w;
            float4 vv = *(const float4*)(g_qkvb + gb + 2 * C);
            *(float4*)(Vs + r * 64 + dc) = vv;
        }
        __syncthreads();

        float sc[4][2];
        #pragma unroll
        for (int qi = 0; qi < 4; qi++) { sc[qi][0] = 0.f; sc[qi][1] = 0.f; }
        #pragma unroll 8
        for (int d = 0; d < 32; d++) {
            float k0 = Ks[lane * KSTR + d];
            float k1 = Ks[(lane + 32) * KSTR + d];
            #pragma unroll
            for (int qi = 0; qi < 4; qi++) {
                float qd = __shfl_sync(0xffffffffu, q[qi][0], d);
                sc[qi][0] = fmaf(qd, k0, sc[qi][0]);
                sc[qi][1] = fmaf(qd, k1, sc[qi][1]);
            }
        }
        #pragma unroll 8
        for (int d = 0; d < 32; d++) {
            float k0 = Ks[lane * KSTR + 32 + d];
            float k1 = Ks[(lane + 32) * KSTR + 32 + d];
            #pragma unroll
            for (int qi = 0; qi < 4; qi++) {
                float qd = __shfl_sync(0xffffffffu, q[qi][1], d);
                sc[qi][0] = fmaf(qd, k0, sc[qi][0]);
                sc[qi][1] = fmaf(qd, k1, sc[qi][1]);
            }
        }

        int s0 = c * 64 + lane, s1 = s0 + 32;
        #pragma unroll
        for (int qi = 0; qi < 4; qi++) {
            int tq = qbase + qi;
            float a0 = (s0 <= tq) ? sc[qi][0] : -1e30f;
            float a1 = (s1 <= tq) ? sc[qi][1] : -1e30f;
            float cm = fmaxf(a0, a1);
            #pragma unroll
            for (int off = 16; off; off >>= 1)
                cm = fmaxf(cm, __shfl_xor_sync(0xffffffffu, cm, off));
            float nm = fmaxf(m[qi], cm);
            float fac = __expf(m[qi] - nm);
            float p0 = __expf(a0 - nm);
            float p1 = __expf(a1 - nm);
            float ps = p0 + p1;
            #pragma unroll
            for (int off = 16; off; off >>= 1)
                ps += __shfl_xor_sync(0xffffffffu, ps, off);
            m[qi] = nm;
            l[qi] = l[qi] * fac + ps;
            o[qi][0] *= fac; o[qi][1] *= fac;
            Ps[w][qi][lane]      = p0;
            Ps[w][qi][lane + 32] = p1;
        }
        __syncwarp();
        #pragma unroll 4
        for (int s = 0; s < 64; s++) {
            float v0 = Vs[s * 64 + lane];
            float v1 = Vs[s * 64 + lane + 32];
            #pragma unroll
            for (int qi = 0; qi < 4; qi++) {
                float pv = Ps[w][qi][s];
                o[qi][0] = fmaf(pv, v0, o[qi][0]);
                o[qi][1] = fmaf(pv, v1, o[qi][1]);
            }
        }
    }

    #pragma unroll
    for (int qi = 0; qi < 4; qi++) {
        float inv = 1.f / l[qi];
        long long base = (long long)(b * TT + qbase + qi) * C + h * HD;
        g_att[base + lane]      = tf32r(o[qi][0] * inv);
        g_att[base + lane + 32] = tf32r(o[qi][1] * inv);
    }
}

// ---------------------------------------------------------------------------
static const int SIG_E[20] = {
    8192, 12288000, 98304, 2304, 2304, 884736, 884736, 884736, 884736, 2304,
    2304, 2304, 3538944, 9216, 3538944, 2304, 384, 384, 12288000, 32000};
static const int ALPHA_E[20] = {
    9216, 2304, 8192, 32000, 12288000, 2304, 2304, 2304, 2304, 384, 384,
    98304, 12288000, 3538944, 3538944, 884736, 884736, 2304, 884736, 884736};
static const int ALPHA_TO_SIG[20] = {
    13, 15, 0, 19, 18, 4, 3, 11, 10, 17, 16, 2, 1, 12, 14, 6, 8, 9, 5, 7};
static const int ALPHA_IDX_POS = 2;
static const int FSIZES[19] = {
    12288000, 98304, 2304, 2304, 884736, 884736, 884736, 884736, 2304,
    2304, 2304, 3538944, 9216, 3538944, 2304, 384, 384, 12288000, 32000};
static const int FROUND[19] = {
    0, 0, 0, 0, 1, 1, 1, 1, 0, 0, 0, 1, 0, 1, 0, 0, 0, 1, 0};

static bool match_pat(const int* s, const int* E, int idx_pos,
                      int fmult, int idx_mult) {
    for (int i = 0; i < 20; i++) {
        long long expect = (long long)E[i] * ((i == idx_pos) ? idx_mult : fmult);
        if ((long long)s[i] != expect) return false;
    }
    return true;
}

extern "C" void kernel_launch(void* const* d_in, const int* in_sizes, int n_in,
                              void* d_out, int out_size) {
    if (n_in != 20) return;

    int in_mode = -2;
    bool alpha = false;
    if      (match_pat(in_sizes, SIG_E,   0,             1, 1)) { in_mode = -1; }
    else if (match_pat(in_sizes, ALPHA_E, ALPHA_IDX_POS, 1, 1)) { in_mode = -1; alpha = true; }
    else if (match_pat(in_sizes, SIG_E,   0,             4, 4)) { in_mode = 0; }
    else if (match_pat(in_sizes, ALPHA_E, ALPHA_IDX_POS, 4, 4)) { in_mode = 0; alpha = true; }
    else if (match_pat(in_sizes, SIG_E,   0,             2, 4)) { in_mode = 1; }
    else if (match_pat(in_sizes, ALPHA_E, ALPHA_IDX_POS, 2, 4)) { in_mode = 1; alpha = true; }
    if (in_mode == -2) return;

    const void* p[20];
    if (alpha) { for (int i = 0; i < 20; i++) p[ALPHA_TO_SIG[i]] = d_in[i]; }
    else       { for (int i = 0; i < 20; i++) p[i] = d_in[i]; }

    long long osz = (long long)out_size;
    const long long OE = (long long)M_TOK * V;
    int out_mode; int lm_rows;
    if      (osz == OE)     { out_mode = -1; lm_rows = M_TOK; }
    else if (osz == 4 * OE) { out_mode = 0;  lm_rows = M_TOK; }
    else if (osz == 2 * OE) { out_mode = 1;  lm_rows = M_TOK; }
    else                    { out_mode = 0;  lm_rows = 0;     }

    const int* idx = (const int*)p[0];

    flags_kernel<<<1, 256>>>(p[1], in_mode, out_mode);
    long long off[19];
    {
        long long o = 0;
        for (int i = 0; i < 19; i++) {
            off[i] = o;
            convert_kernel<<<(FSIZES[i] + 255) / 256, 256>>>(p[i + 1], o, FSIZES[i], FROUND[i]);
            o += FSIZES[i];
        }
    }
    const long long oTok = off[0],  oPos = off[1];
    const long long oL1g = off[2],  oL1b = off[3];
    const long long oWq = off[4], oWk = off[5], oWv = off[6], oWo = off[7];
    const long long oWob = off[8], oL2g = off[9], oL2b = off[10];
    const long long oW1 = off[11], oB1 = off[12], oW2 = off[13], oB2 = off[14];
    const long long oLfg = off[15], oLfb = off[16], oLmw = off[17], oLmb = off[18];
    const long long oQKVW = WBUF_ORIG;

    pack_qkv<<<(NL * C * C3 + 255) / 256, 256>>>(oWq, oWk, oWv, oQKVW);

    embed_kernel<<<M_TOK, C>>>(idx, oTok, oPos);

    dim3 gQKV(C3 / 128, M_TOK / 128);
    dim3 gC  (C  / 128, M_TOK / 128);
    dim3 gF  (FF / 128, M_TOK / 128);
    dim3 gV  (V  / 128, M_TOK / 128);

    // scratch selectors: 0=x 1=h 5=att 6=mlp 7=qkv
    for (int l = 0; l < NL; l++) {
        long long qkv_l = oQKVW + (long long)l * C * C3;
        long long wo_l  = oWo + (long long)l * C * C;
        long long wob_l = oWob + (long long)l * C;
        long long w1_l  = oW1 + (long long)l * C * FF;
        long long b1_l  = oB1 + (long long)l * FF;
        long long w2_l  = oW2 + (long long)l * FF * C;
        long long b2_l  = oB2 + (long long)l * C;

        ln_kernel<<<M_TOK, 128>>>(0, oL1g + l * C, oL1b + l * C, 1, 1);
        mma_gemm<false,false,false,false,false><<<gQKV, 256>>>(1, qkv_l, 0, 7, nullptr, M_TOK, C3, C, M_TOK);
        flash_attn<<<BB * HN * 8, 256>>>();
        mma_gemm<true,false,true,false,false><<<gC, 256>>>(5, wo_l, wob_l, 0, nullptr, M_TOK, C, C, M_TOK);
        ln_kernel<<<M_TOK, 128>>>(0, oL2g + l * C, oL2b + l * C, 1, 1);
        mma_gemm<true,true,false,true,false><<<gF, 256>>>(1, w1_l, b1_l, 6, nullptr, M_TOK, FF, C, M_TOK);
        mma_gemm<true,false,true,false,false><<<gC, 256>>>(6, w2_l, b2_l, 0, nullptr, M_TOK, C, FF, M_TOK);
    }

    ln_kernel<<<M_TOK, 128>>>(0, oLfg, oLfb, 1, 1);
    mma_gemm<true,false,false,false,true><<<gV, 256>>>(1, oLmw, oLmb, 0, d_out, M_TOK, V, C, lm_rows);
}

// round 15
// speedup vs baseline: 3.3444x; 3.3444x over previous
#include <cuda_runtime.h>
#include <cuda_bf16.h>
#include <cuda_fp16.h>
#include <cstdint>

// ---------------------------------------------------------------------------
// BarbershopTransformer: 6-layer GPT forward, B=32 T=256 C=384 H=6 D=64 V=32000
// Round 15: fp16 mma.sync (m16n8k16) GEMM on R8 skeleton; weights pre-packed
// to half2 (k-pairs); fused QKV; flash attention.
// ---------------------------------------------------------------------------

#define NL    6
#define C     384
#define HN    6
#define HD    64
#define TT    256
#define BB    32
#define M_TOK (BB*TT)          // 8192
#define FF    (4*C)            // 1536
#define V     32000
#define C3    (3*C)            // 1152

__device__ float g_x   [M_TOK*C];
__device__ float g_h   [M_TOK*C];
__device__ float g_att [M_TOK*C];
__device__ float g_mlp [M_TOK*FF];
__device__ float g_qkvb[M_TOK*C3];

#define WBUF_ORIG 35349248
#define WBUF_TOTAL (WBUF_ORIG + NL*C*C3)
__device__ float g_wbuf[WBUF_TOTAL];

// half2-packed weights (k even/odd pairs): [K/2 rows][N cols] of uint32
#define H_QKV 0LL
#define H_WO  1327104LL
#define H_W1  1769472LL
#define H_W2  3538944LL
#define H_LM  5308416LL
#define H_TOTAL 11452416LL
__device__ uint32_t g_wh[H_TOTAL];

__device__ int g_in_bf16;
__device__ int g_out_bf16;

__device__ __forceinline__ float* buf_sel(int s) {
    switch (s) {
        case 0: return g_x;
        case 1: return g_h;
        case 5: return g_att;
        case 6: return g_mlp;
        default: return g_qkvb;   // 7
    }
}

__device__ __forceinline__ uint32_t pack_h2(float lo, float hi) {
    __half2 h = __floats2half2_rn(lo, hi);
    return *(uint32_t*)&h;
}

// ---------------------------------------------------------------------------
__global__ void flags_kernel(const void* buf, int in_mode, int out_mode) {
    __shared__ int sh;
    int tid = threadIdx.x;
    if (tid == 0) sh = 0;
    __syncthreads();
    if (in_mode < 0) {
        const __nv_bfloat16* s = (const __nv_bfloat16*)buf;
        int cnt = 0;
        for (int i = tid; i < 4096; i += 256) {
            float f = __bfloat162float(s[i]);
            if (!isfinite(f) || fabsf(f) > 8.0f) cnt++;
        }
        atomicAdd(&sh, cnt);
    }
    __syncthreads();
    if (tid == 0) {
        int in_bf16 = (in_mode < 0) ? ((sh > 64) ? 0 : 1) : in_mode;
        g_in_bf16  = in_bf16;
        g_out_bf16 = (out_mode < 0) ? in_bf16 : out_mode;
    }
}

__global__ void convert_kernel(const void* src, long long off, int n) {
    int i = blockIdx.x * blockDim.x + threadIdx.x;
    if (i >= n) return;
    float vv;
    if (g_in_bf16) vv = __bfloat162float(((const __nv_bfloat16*)src)[i]);
    else           vv = ((const float*)src)[i];
    long long o = off + i;
    if (o >= 0 && o < WBUF_TOTAL) g_wbuf[o] = vv;
}

// Pack Wq|Wk|Wv -> [NL][C][3C] (f32, staging buffer)
__global__ void pack_qkv(long long oWq, long long oWk, long long oWv, long long dst) {
    int i = blockIdx.x * blockDim.x + threadIdx.x;
    if (i >= NL * C * C3) return;
    int n3  = i % C3;
    int rem = i / C3;
    int part = n3 / C, n = n3 % C;
    long long src = (part == 0 ? oWq : part == 1 ? oWk : oWv) + (long long)rem * C + n;
    g_wbuf[dst + i] = g_wbuf[src];
}

// Pack f32 weights [L][K][N] -> half2 k-pairs [L][K/2][N] in g_wh
__global__ void pack_half(long long srcOff, long long dstOff, int K2, int N, int L) {
    int i = blockIdx.x * blockDim.x + threadIdx.x;
    if (i >= L * K2 * N) return;
    int n = i % N;
    int rem = i / N;            // l*K2 + k2
    int k2 = rem % K2, l = rem / K2;
    const float* s = g_wbuf + srcOff + ((long long)l * K2 * 2 + 2 * k2) * N + n;
    g_wh[dstOff + i] = pack_h2(s[0], s[N]);
}

// ---------------------------------------------------------------------------
__global__ void embed_kernel(const int* __restrict__ idx,
                             long long tokOff, long long posOff) {
    int m = blockIdx.x;
    int c = threadIdx.x;
    int t = m & (TT - 1);
    int tk = idx[m];
    if ((unsigned)tk >= (unsigned)V) tk = 0;
    const float* tok = g_wbuf + tokOff;
    const float* pos = g_wbuf + posOff;
    g_x[m * C + c] = tok[tk * C + c] + pos[t * C + c];
}

// ---------------------------------------------------------------------------
__global__ void ln_kernel(int inSel, long long gOff, long long bOff, int outSel) {
    __shared__ float red[4];
    __shared__ float stat[2];
    const float* x = buf_sel(inSel);
    float* out     = buf_sel(outSel);
    const float* g = g_wbuf + gOff;
    const float* b = g_wbuf + bOff;
    int row = blockIdx.x, tid = threadIdx.x;
    const float* xr = x + (size_t)row * C;
    float v0 = xr[tid], v1 = xr[tid + 128], v2 = xr[tid + 256];
    float s = v0 + v1 + v2;
    #pragma unroll
    for (int o = 16; o; o >>= 1) s += __shfl_xor_sync(0xffffffffu, s, o);
    if ((tid & 31) == 0) red[tid >> 5] = s;
    __syncthreads();
    if (tid == 0) stat[0] = (red[0] + red[1] + red[2] + red[3]) * (1.0f / C);
    __syncthreads();
    float m = stat[0];
    float d0 = v0 - m, d1 = v1 - m, d2 = v2 - m;
    float q = d0 * d0 + d1 * d1 + d2 * d2;
    #pragma unroll
    for (int o = 16; o; o >>= 1) q += __shfl_xor_sync(0xffffffffu, q, o);
    if ((tid & 31) == 0) red[tid >> 5] = q;
    __syncthreads();
    if (tid == 0)
        stat[1] = rsqrtf((red[0] + red[1] + red[2] + red[3]) * (1.0f / C) + 1e-5f);
    __syncthreads();
    float r = stat[1];
    float* o = out + (size_t)row * C;
    o[tid]       = d0 * r * g[tid]       + b[tid];
    o[tid + 128] = d1 * r * g[tid + 128] + b[tid + 128];
    o[tid + 256] = d2 * r * g[tid + 256] + b[tid + 256];
}

// ---------------------------------------------------------------------------
__device__ __forceinline__ void mma_f16(float& c0, float& c1, float& c2, float& c3,
                                        uint32_t a0, uint32_t a1, uint32_t a2, uint32_t a3,
                                        uint32_t b0, uint32_t b1) {
    asm volatile(
        "mma.sync.aligned.m16n8k16.row.col.f32.f16.f16.f32 "
        "{%0,%1,%2,%3}, {%4,%5,%6,%7}, {%8,%9}, {%0,%1,%2,%3};\n"
        : "+f"(c0), "+f"(c1), "+f"(c2), "+f"(c3)
        : "r"(a0), "r"(a1), "r"(a2), "r"(a3), "r"(b0), "r"(b1));
}

// ---------------------------------------------------------------------------
// fp16 GEMM: C[M,N] = A[M,K](f32) @ Wh[K/2,N](half2 k-pairs). BM=BN=128,
// BK=32, 256 thr (8 warps of 64x32), single-buffered (R8-proven loop shape).
// As: packed k-pairs [128 rows][16 k2 + pad4] words; Bs: [16 k2][128 + pad8].
template<bool BIAS, bool RELU, bool RES, bool DYNOUT>
__global__ void __launch_bounds__(256, 2)
mma_gemm(int aSel, long long bOff, long long biasOff,
         int outSel, void* dOutPtr, int M, int N, int K, int Mlim) {
    __shared__ uint32_t As[128 * 20];   // 10240 B
    __shared__ uint32_t Bs[16 * 136];   //  8704 B
    const float*    A  = buf_sel(aSel);
    const uint32_t* Bh = g_wh + bOff;
    const float*    bi = g_wbuf + biasOff;

    int tid = threadIdx.x;
    int warp = tid >> 5, lane = tid & 31;
    int wm = warp >> 2;          // 0..1  (64-row slab)
    int wn = warp & 3;           // 0..3  (32-col slab)
    int g = lane >> 2, t = lane & 3;
    int bm = blockIdx.y * 128, bn = blockIdx.x * 128;

    float acc[4][4][4];
    #pragma unroll
    for (int mi = 0; mi < 4; mi++)
        #pragma unroll
        for (int ni = 0; ni < 4; ni++)
            #pragma unroll
            for (int cc = 0; cc < 4; cc++) acc[mi][ni][cc] = 0.f;

    int niter = K >> 5;
    for (int it = 0; it < niter; it++) {
        int k0 = it << 5;
        // stage A: 128 rows x 32 k (f32 -> half2 pairs), 2 ops/thread
        #pragma unroll
        for (int u = 0; u < 2; u++) {
            int f = tid + u * 256;              // 0..511
            int row = f >> 2, kc = (f & 3) * 8;
            const float* src = A + (size_t)(bm + row) * K + k0 + kc;
            float4 x0 = *(const float4*)src;
            float4 x1 = *(const float4*)(src + 4);
            uint4 pk = make_uint4(pack_h2(x0.x, x0.y), pack_h2(x0.z, x0.w),
                                  pack_h2(x1.x, x1.y), pack_h2(x1.z, x1.w));
            *(uint4*)(As + row * 20 + (kc >> 1)) = pk;
        }
        // stage B: 16 k2-rows x 128 cols (raw uint4 copy), 2 ops/thread
        int k02 = k0 >> 1;
        #pragma unroll
        for (int u = 0; u < 2; u++) {
            int f = tid + u * 256;
            int k2 = f >> 5, nc = (f & 31) * 4;
            uint4 v = *(const uint4*)(Bh + (size_t)(k02 + k2) * N + bn + nc);
            *(uint4*)(Bs + k2 * 136 + nc) = v;
        }
        __syncthreads();

        #pragma unroll
        for (int b = 0; b < 2; b++) {          // two k16 blocks
            uint32_t af[4][4];
            #pragma unroll
            for (int mi = 0; mi < 4; mi++) {
                int row = wm * 64 + mi * 16;
                int kb = b * 8 + t;
                af[mi][0] = As[(row + g)     * 20 + kb];
                af[mi][1] = As[(row + g + 8) * 20 + kb];
                af[mi][2] = As[(row + g)     * 20 + kb + 4];
                af[mi][3] = As[(row + g + 8) * 20 + kb + 4];
            }
            uint32_t bf[4][2];
            #pragma unroll
            for (int ni = 0; ni < 4; ni++) {
                int col = wn * 32 + ni * 8 + g;
                bf[ni][0] = Bs[(b * 8 + t)     * 136 + col];
                bf[ni][1] = Bs[(b * 8 + t + 4) * 136 + col];
            }
            #pragma unroll
            for (int mi = 0; mi < 4; mi++)
                #pragma unroll
                for (int ni = 0; ni < 4; ni++)
                    mma_f16(acc[mi][ni][0], acc[mi][ni][1],
                            acc[mi][ni][2], acc[mi][ni][3],
                            af[mi][0], af[mi][1], af[mi][2], af[mi][3],
                            bf[ni][0], bf[ni][1]);
        }
        __syncthreads();
    }

    // epilogue (same c-fragment mapping as R8)
    bool store_bf16 = DYNOUT ? (g_out_bf16 != 0) : false;
    float* outBuf = DYNOUT ? nullptr : buf_sel(outSel);
    #pragma unroll
    for (int mi = 0; mi < 4; mi++) {
        #pragma unroll
        for (int ni = 0; ni < 4; ni++) {
            int col = bn + wn * 32 + ni * 8 + t * 2;
            float b0 = 0.f, b1 = 0.f;
            if (BIAS) { b0 = bi[col]; b1 = bi[col + 1]; }
            #pragma unroll
            for (int half = 0; half < 2; half++) {
                int row = bm + wm * 64 + mi * 16 + g + half * 8;
                if (row >= Mlim) continue;
                float v0 = acc[mi][ni][half * 2 + 0];
                float v1 = acc[mi][ni][half * 2 + 1];
                if (BIAS) { v0 += b0; v1 += b1; }
                if (RELU) { v0 = fmaxf(v0, 0.f); v1 = fmaxf(v1, 0.f); }
                long long base = (long long)row * N + col;
                if (RES) {
                    float2 rr = *(const float2*)(g_x + base);
                    v0 += rr.x; v1 += rr.y;
                }
                if (DYNOUT) {
                    if (store_bf16) {
                        __nv_bfloat162 pk = __floats2bfloat162_rn(v0, v1);
                        *(__nv_bfloat162*)((__nv_bfloat16*)dOutPtr + base) = pk;
                    } else {
                        *(float2*)((float*)dOutPtr + base) = make_float2(v0, v1);
                    }
                } else {
                    *(float2*)(outBuf + base) = make_float2(v0, v1);
                }
            }
        }
    }
}

// ---------------------------------------------------------------------------
// Flash attention on fused qkv buffer [M,1152]: q|k|v at col 0/384/768.
#define KSTR 65
#define QS   C3
__global__ void __launch_bounds__(256)
flash_attn() {
    __shared__ float Ks[64 * KSTR];
    __shared__ float Vs[64 * 64];
    __shared__ float Ps[8][4][64];
    int blk = blockIdx.x;
    int qt = blk & 7;
    int bh = blk >> 3;
    int b = bh / HN, h = bh % HN;
    int tid = threadIdx.x, w = tid >> 5, lane = tid & 31;
    int qbase = qt * 32 + w * 4;
    const float scale = rsqrtf((float)C);

    float q[4][2];
    #pragma unroll
    for (int qi = 0; qi < 4; qi++) {
        long long base = (long long)(b * TT + qbase + qi) * QS + h * HD;
        q[qi][0] = g_qkvb[base + lane]      * scale;
        q[qi][1] = g_qkvb[base + lane + 32] * scale;
    }
    float o[4][2];
    float m[4], l[4];
    #pragma unroll
    for (int qi = 0; qi < 4; qi++) {
        o[qi][0] = o[qi][1] = 0.f;
        m[qi] = -1e30f; l[qi] = 0.f;
    }

    int nch = (qt * 32 + 31) / 64 + 1;
    for (int c = 0; c < nch; c++) {
        __syncthreads();
        #pragma unroll
        for (int u = 0; u < 4; u++) {
            int f = tid + u * 256;
            int r = f >> 4, dc = (f & 15) * 4;
            long long gb = (long long)(b * TT + c * 64 + r) * QS + h * HD + dc;
            float4 kv = *(const float4*)(g_qkvb + gb + C);
            Ks[r * KSTR + dc]     = kv.x;
            Ks[r * KSTR + dc + 1] = kv.y;
            Ks[r * KSTR + dc + 2] = kv.z;
            Ks[r * KSTR + dc + 3] = kv.w;
            float4 vv = *(const float4*)(g_qkvb + gb + 2 * C);
            *(float4*)(Vs + r * 64 + dc) = vv;
        }
        __syncthreads();

        float sc[4][2];
        #pragma unroll
        for (int qi = 0; qi < 4; qi++) { sc[qi][0] = 0.f; sc[qi][1] = 0.f; }
        #pragma unroll 8
        for (int d = 0; d < 32; d++) {
            float k0 = Ks[lane * KSTR + d];
            float k1 = Ks[(lane + 32) * KSTR + d];
            #pragma unroll
            for (int qi = 0; qi < 4; qi++) {
                float qd = __shfl_sync(0xffffffffu, q[qi][0], d);
                sc[qi][0] = fmaf(qd, k0, sc[qi][0]);
                sc[qi][1] = fmaf(qd, k1, sc[qi][1]);
            }
        }
        #pragma unroll 8
        for (int d = 0; d < 32; d++) {
            float k0 = Ks[lane * KSTR + 32 + d];
            float k1 = Ks[(lane + 32) * KSTR + 32 + d];
            #pragma unroll
            for (int qi = 0; qi < 4; qi++) {
                float qd = __shfl_sync(0xffffffffu, q[qi][1], d);
                sc[qi][0] = fmaf(qd, k0, sc[qi][0]);
                sc[qi][1] = fmaf(qd, k1, sc[qi][1]);
            }
        }

        int s0 = c * 64 + lane, s1 = s0 + 32;
        #pragma unroll
        for (int qi = 0; qi < 4; qi++) {
            int tq = qbase + qi;
            float a0 = (s0 <= tq) ? sc[qi][0] : -1e30f;
            float a1 = (s1 <= tq) ? sc[qi][1] : -1e30f;
            float cm = fmaxf(a0, a1);
            #pragma unroll
            for (int off = 16; off; off >>= 1)
                cm = fmaxf(cm, __shfl_xor_sync(0xffffffffu, cm, off));
            float nm = fmaxf(m[qi], cm);
            float fac = __expf(m[qi] - nm);
            float p0 = __expf(a0 - nm);
            float p1 = __expf(a1 - nm);
            float ps = p0 + p1;
            #pragma unroll
            for (int off = 16; off; off >>= 1)
                ps += __shfl_xor_sync(0xffffffffu, ps, off);
            m[qi] = nm;
            l[qi] = l[qi] * fac + ps;
            o[qi][0] *= fac; o[qi][1] *= fac;
            Ps[w][qi][lane]      = p0;
            Ps[w][qi][lane + 32] = p1;
        }
        __syncwarp();
        #pragma unroll 4
        for (int s = 0; s < 64; s++) {
            float v0 = Vs[s * 64 + lane];
            float v1 = Vs[s * 64 + lane + 32];
            #pragma unroll
            for (int qi = 0; qi < 4; qi++) {
                float pv = Ps[w][qi][s];
                o[qi][0] = fmaf(pv, v0, o[qi][0]);
                o[qi][1] = fmaf(pv, v1, o[qi][1]);
            }
        }
    }

    #pragma unroll
    for (int qi = 0; qi < 4; qi++) {
        float inv = 1.f / l[qi];
        long long base = (long long)(b * TT + qbase + qi) * C + h * HD;
        g_att[base + lane]      = o[qi][0] * inv;
        g_att[base + lane + 32] = o[qi][1] * inv;
    }
}

// ---------------------------------------------------------------------------
static const int SIG_E[20] = {
    8192, 12288000, 98304, 2304, 2304, 884736, 884736, 884736, 884736, 2304,
    2304, 2304, 3538944, 9216, 3538944, 2304, 384, 384, 12288000, 32000};
static const int ALPHA_E[20] = {
    9216, 2304, 8192, 32000, 12288000, 2304, 2304, 2304, 2304, 384, 384,
    98304, 12288000, 3538944, 3538944, 884736, 884736, 2304, 884736, 884736};
static const int ALPHA_TO_SIG[20] = {
    13, 15, 0, 19, 18, 4, 3, 11, 10, 17, 16, 2, 1, 12, 14, 6, 8, 9, 5, 7};
static const int ALPHA_IDX_POS = 2;
static const int FSIZES[19] = {
    12288000, 98304, 2304, 2304, 884736, 884736, 884736, 884736, 2304,
    2304, 2304, 3538944, 9216, 3538944, 2304, 384, 384, 12288000, 32000};

static bool match_pat(const int* s, const int* E, int idx_pos,
                      int fmult, int idx_mult) {
    for (int i = 0; i < 20; i++) {
        long long expect = (long long)E[i] * ((i == idx_pos) ? idx_mult : fmult);
        if ((long long)s[i] != expect) return false;
    }
    return true;
}

extern "C" void kernel_launch(void* const* d_in, const int* in_sizes, int n_in,
                              void* d_out, int out_size) {
    if (n_in != 20) return;

    int in_mode = -2;
    bool alpha = false;
    if      (match_pat(in_sizes, SIG_E,   0,             1, 1)) { in_mode = -1; }
    else if (match_pat(in_sizes, ALPHA_E, ALPHA_IDX_POS, 1, 1)) { in_mode = -1; alpha = true; }
    else if (match_pat(in_sizes, SIG_E,   0,             4, 4)) { in_mode = 0; }
    else if (match_pat(in_sizes, ALPHA_E, ALPHA_IDX_POS, 4, 4)) { in_mode = 0; alpha = true; }
    else if (match_pat(in_sizes, SIG_E,   0,             2, 4)) { in_mode = 1; }
    else if (match_pat(in_sizes, ALPHA_E, ALPHA_IDX_POS, 2, 4)) { in_mode = 1; alpha = true; }
    if (in_mode == -2) return;

    const void* p[20];
    if (alpha) { for (int i = 0; i < 20; i++) p[ALPHA_TO_SIG[i]] = d_in[i]; }
    else       { for (int i = 0; i < 20; i++) p[i] = d_in[i]; }

    long long osz = (long long)out_size;
    const long long OE = (long long)M_TOK * V;
    int out_mode; int lm_rows;
    if      (osz == OE)     { out_mode = -1; lm_rows = M_TOK; }
    else if (osz == 4 * OE) { out_mode = 0;  lm_rows = M_TOK; }
    else if (osz == 2 * OE) { out_mode = 1;  lm_rows = M_TOK; }
    else                    { out_mode = 0;  lm_rows = 0;     }

    const int* idx = (const int*)p[0];

    flags_kernel<<<1, 256>>>(p[1], in_mode, out_mode);
    long long off[19];
    {
        long long o = 0;
        for (int i = 0; i < 19; i++) {
            off[i] = o;
            convert_kernel<<<(FSIZES[i] + 255) / 256, 256>>>(p[i + 1], o, FSIZES[i]);
            o += FSIZES[i];
        }
    }
    const long long oTok = off[0],  oPos = off[1];
    const long long oL1g = off[2],  oL1b = off[3];
    const long long oWq = off[4], oWk = off[5], oWv = off[6], oWo = off[7];
    const long long oWob = off[8], oL2g = off[9], oL2b = off[10];
    const long long oW1 = off[11], oB1 = off[12], oW2 = off[13], oB2 = off[14];
    const long long oLfg = off[15], oLfb = off[16], oLmw = off[17], oLmb = off[18];
    const long long oQKVW = WBUF_ORIG;

    pack_qkv<<<(NL * C * C3 + 255) / 256, 256>>>(oWq, oWk, oWv, oQKVW);
    // pack all weights to half2 k-pairs
    pack_half<<<(NL * (C/2) * C3 + 255) / 256, 256>>>(oQKVW, H_QKV, C/2, C3, NL);
    pack_half<<<(NL * (C/2) * C  + 255) / 256, 256>>>(oWo,   H_WO,  C/2, C,  NL);
    pack_half<<<(NL * (C/2) * FF + 255) / 256, 256>>>(oW1,   H_W1,  C/2, FF, NL);
    pack_half<<<(NL * (FF/2) * C + 255) / 256, 256>>>(oW2,   H_W2,  FF/2, C, NL);
    pack_half<<<((C/2) * V + 255) / 256, 256>>>(oLmw, H_LM, C/2, V, 1);

    embed_kernel<<<M_TOK, C>>>(idx, oTok, oPos);

    dim3 gQKV(C3 / 128, M_TOK / 128);   // (9, 64)
    dim3 gC  (C  / 128, M_TOK / 128);   // (3, 64)
    dim3 gF  (FF / 128, M_TOK / 128);   // (12, 64)
    dim3 gV  (V  / 128, M_TOK / 128);   // (250, 64)

    // scratch selectors: 0=x 1=h 5=att 6=mlp 7=qkv
    for (int l = 0; l < NL; l++) {
        long long hqkv_l = H_QKV + (long long)l * (C/2) * C3;
        long long hwo_l  = H_WO  + (long long)l * (C/2) * C;
        long long hw1_l  = H_W1  + (long long)l * (C/2) * FF;
        long long hw2_l  = H_W2  + (long long)l * (FF/2) * C;
        long long wob_l  = oWob + (long long)l * C;
        long long b1_l   = oB1 + (long long)l * FF;
        long long b2_l   = oB2 + (long long)l * C;

        ln_kernel<<<M_TOK, 128>>>(0, oL1g + l * C, oL1b + l * C, 1);
        mma_gemm<false,false,false,false><<<gQKV, 256>>>(1, hqkv_l, 0, 7, nullptr, M_TOK, C3, C, M_TOK);
        flash_attn<<<BB * HN * 8, 256>>>();
        mma_gemm<true,false,true,false><<<gC, 256>>>(5, hwo_l, wob_l, 0, nullptr, M_TOK, C, C, M_TOK);
        ln_kernel<<<M_TOK, 128>>>(0, oL2g + l * C, oL2b + l * C, 1);
        mma_gemm<true,true,false,false><<<gF, 256>>>(1, hw1_l, b1_l, 6, nullptr, M_TOK, FF, C, M_TOK);
        mma_gemm<true,false,true,false><<<gC, 256>>>(6, hw2_l, b2_l, 0, nullptr, M_TOK, C, FF, M_TOK);
    }

    ln_kernel<<<M_TOK, 128>>>(0, oLfg, oLfb, 1);
    mma_gemm<true,false,false,true><<<gV, 256>>>(1, H_LM, oLmb, 0, d_out, M_TOK, V, C, lm_rows);
}